// round 5
// baseline (speedup 1.0000x reference)
#include <cuda_runtime.h>

#define B_   128
#define C_   1024
#define HW_  256
#define S_   32
#define EMB_ 256
#define TC   64     // channels per block (kernel 2)
#define PC   16     // p-rows per smem chunk (kernel 2)
#define NCHUNK (HW_ / PC)   // 16

typedef unsigned long long u64;

// ---- packed f32x2 helpers (sm_103a FFMA2 path) ----
__device__ __forceinline__ u64 pk2(float x, float y) {
  u64 r; asm("mov.b64 %0, {%1, %2};" : "=l"(r) : "f"(x), "f"(y)); return r;
}
__device__ __forceinline__ void upk2(u64 v, float& x, float& y) {
  asm("mov.b64 {%0, %1}, %2;" : "=f"(x), "=f"(y) : "l"(v));
}
__device__ __forceinline__ void fma2(u64& d, u64 a, u64 b) {   // d += a*b (2 lanes)
  asm("fma.rn.f32x2 %0, %1, %2, %0;" : "+l"(d) : "l"(a), "l"(b));
}
__device__ __forceinline__ u64 add2(u64 a, u64 b) {
  u64 r; asm("add.rn.f32x2 %0, %1, %2;" : "=l"(r) : "l"(a), "l"(b)); return r;
}

// we transposed: [b][p][s]  (p = idf index 0..255, s = token 0..31), 4 MB scratch
__device__ float g_we[(size_t)B_ * HW_ * S_];

// ---------------------------------------------------------------------------
// Kernel 1: we_t[b][p][s] = sum_e word_emb[b][s][e] * ck[e][p] + bias[p]
// One block per batch; thread t owns p = t, all 32 s packed in f32x2 registers.
// ---------------------------------------------------------------------------
__global__ __launch_bounds__(256) void we_proj_kernel(
    const float* __restrict__ word_emb,
    const float* __restrict__ ck,
    const float* __restrict__ bias) {
  __shared__ float emb_t[EMB_][S_];  // [e][s], 32 KB
  const int b = blockIdx.x;
  const int t = threadIdx.x;
  const float* wb = word_emb + (size_t)b * S_ * EMB_;

  // transpose-load word_emb[b] into smem: conflict-free STS, L1-amortized LDG
  for (int j = t; j < S_ * EMB_; j += 256) {
    int s = j & (S_ - 1);
    int e = j >> 5;
    emb_t[e][s] = wb[s * EMB_ + e];
  }
  __syncthreads();

  const int p = t;
  const float bv = bias[p];
  u64 acc2[S_ / 2];                       // 16 packed pairs = 32 s-values
  const u64 bv2 = pk2(bv, bv);
#pragma unroll
  for (int q = 0; q < S_ / 2; q++) acc2[q] = bv2;

#pragma unroll 4
  for (int e = 0; e < EMB_; e++) {
    const float ckv = ck[e * EMB_ + p];   // coalesced LDG, L2-resident (256 KB)
    const u64 c2 = pk2(ckv, ckv);
    const ulonglong2* er = (const ulonglong2*)emb_t[e];  // 8 x LDS.128 broadcast
#pragma unroll
    for (int q = 0; q < 8; q++) {
      ulonglong2 v = er[q];               // v.x = s(4q,4q+1), v.y = s(4q+2,4q+3)
      fma2(acc2[2*q + 0], v.x, c2);
      fma2(acc2[2*q + 1], v.y, c2);
    }
  }

  ulonglong2* o = (ulonglong2*)(g_we + ((size_t)b * HW_ + p) * S_);
#pragma unroll
  for (int q = 0; q < 8; q++) {
    ulonglong2 v; v.x = acc2[2*q]; v.y = acc2[2*q + 1];
    o[q] = v;
  }
}

// ---------------------------------------------------------------------------
// Kernel 2 (fused): per (b, 64-channel tile):
//   logits[c][s] = sum_p wc[b][p][c] * we_t[b][p][s]   (K=256, double-buffered)
//   attn = softmax_s(logits)            -> gmem + smem
//   out[p][c]   = sum_s we_t[b][p][s] * attn[c][s]     (K=32)
// ---------------------------------------------------------------------------
__global__ __launch_bounds__(256) void attn_kernel(
    const float* __restrict__ wc,
    float* __restrict__ out,
    float* __restrict__ attn_out) {
  __shared__ float we_sm[HW_][S_];              // 32 KB: [p][s]
  // pool aliases: wc double-buffer [2][PC][TC] (2048 f) then attn [TC][33] (2112 f)
  __shared__ __align__(16) float pool[TC * (S_ + 1)];
  float (*wc_sm)[PC][TC]   = (float (*)[PC][TC])pool;
  float (*attn_sm)[S_ + 1] = (float (*)[S_ + 1])pool;

  const int b  = blockIdx.y;
  const int c0 = blockIdx.x * TC;
  const int t  = threadIdx.x;

  // stage we_t[b] (8192 floats) into smem (L2-resident after first tile of b)
  {
    const float4* gw = (const float4*)(g_we + (size_t)b * HW_ * S_);
    float4* sw = (float4*)we_sm;
    for (int i = t; i < HW_ * S_ / 4; i += 256) sw[i] = gw[i];
  }

  // ---- logits: thread owns c = {2*cg, 2*cg+1}, s = 4*sg .. 4*sg+3 ----
  const int cg = t >> 3;   // 0..31
  const int sg = t & 7;    // 0..7
  u64 acc2[2][2];          // [c][s-pair]
  acc2[0][0] = acc2[0][1] = acc2[1][0] = acc2[1][1] = 0ull;  // == {0.f,0.f}

  const float* wcb = wc + (size_t)b * HW_ * C_ + c0;
  const int ldrow = t >> 4;            // 0..15
  const int ldcol = (t & 15) << 2;     // 0,4,..,60
  const float* ldsrc = wcb + (size_t)ldrow * C_ + ldcol;

  float4 pre = *(const float4*)ldsrc;  // preload chunk 0
  *(float4*)&wc_sm[0][ldrow][ldcol] = pre;
  __syncthreads();                     // chunk 0 + we_sm visible

  for (int pcI = 0; pcI < NCHUNK; pcI++) {
    if (pcI + 1 < NCHUNK)              // hide next chunk's LDG behind compute
      pre = *(const float4*)(ldsrc + (size_t)(pcI + 1) * PC * C_);

    const float (*buf)[TC] = wc_sm[pcI & 1];
#pragma unroll
    for (int pp = 0; pp < PC; pp++) {
      float2 w = *(const float2*)&buf[pp][cg * 2];            // LDS.64 broadcast x8
      const u64 wx2 = pk2(w.x, w.x);
      const u64 wy2 = pk2(w.y, w.y);
      ulonglong2 v = *(const ulonglong2*)&we_sm[pcI * PC + pp][sg * 4];  // LDS.128
      fma2(acc2[0][0], v.x, wx2);
      fma2(acc2[0][1], v.y, wx2);
      fma2(acc2[1][0], v.x, wy2);
      fma2(acc2[1][1], v.y, wy2);
    }

    if (pcI + 1 < NCHUNK)
      *(float4*)&wc_sm[(pcI + 1) & 1][ldrow][ldcol] = pre;
    __syncthreads();                   // one barrier per chunk (race-audited)
  }

  float acc[2][4];
  upk2(acc2[0][0], acc[0][0], acc[0][1]);
  upk2(acc2[0][1], acc[0][2], acc[0][3]);
  upk2(acc2[1][0], acc[1][0], acc[1][1]);
  upk2(acc2[1][1], acc[1][2], acc[1][3]);

  // ---- softmax over s (8-lane aligned shuffle groups) ----
  float m0 = fmaxf(fmaxf(acc[0][0], acc[0][1]), fmaxf(acc[0][2], acc[0][3]));
  float m1 = fmaxf(fmaxf(acc[1][0], acc[1][1]), fmaxf(acc[1][2], acc[1][3]));
#pragma unroll
  for (int o = 1; o < 8; o <<= 1) {
    m0 = fmaxf(m0, __shfl_xor_sync(0xffffffffu, m0, o));
    m1 = fmaxf(m1, __shfl_xor_sync(0xffffffffu, m1, o));
  }
  float s0 = 0.f, s1 = 0.f;
#pragma unroll
  for (int j = 0; j < 4; j++) {
    acc[0][j] = __expf(acc[0][j] - m0); s0 += acc[0][j];
    acc[1][j] = __expf(acc[1][j] - m1); s1 += acc[1][j];
  }
#pragma unroll
  for (int o = 1; o < 8; o <<= 1) {
    s0 += __shfl_xor_sync(0xffffffffu, s0, o);
    s1 += __shfl_xor_sync(0xffffffffu, s1, o);
  }
  const float inv0 = 1.f / s0;
  const float inv1 = 1.f / s1;
  // wc_sm dead; attn_sm aliases the pool (all wc reads fenced by final barrier)
#pragma unroll
  for (int j = 0; j < 4; j++) {
    attn_sm[2*cg + 0][4*sg + j] = acc[0][j] * inv0;
    attn_sm[2*cg + 1][4*sg + j] = acc[1][j] * inv1;
  }
  __syncthreads();

  // ---- attn -> gmem (coalesced): attn[b][c0+c][s] ----
  {
    float* ab = attn_out + ((size_t)b * C_ + c0) * S_;
#pragma unroll
    for (int k = 0; k < (TC * S_) / 256; k++) {   // 8 iters
      int idx = t + 256 * k;
      ab[idx] = attn_sm[idx >> 5][idx & 31];
    }
  }

  // ---- epilogue GEMM: out[b][p][c0+oc] = sum_s we_sm[p][s] * attn_sm[oc][s] ----
  {
    const int oc = t & 63;   // channel within tile (coalesced stores)
    const int pg = t >> 6;   // 0..3
    u64 a2[S_ / 2];          // prepacked attn pairs: a2[q] = attn(2q, 2q+1)
#pragma unroll
    for (int q = 0; q < S_ / 2; q++)
      a2[q] = pk2(attn_sm[oc][2*q], attn_sm[oc][2*q + 1]);  // stride-33, conflict-free

    float* ob = out + (size_t)b * HW_ * C_ + c0 + oc;
    for (int k = 0; k < HW_ / 4; k++) {
      const int p = pg * 64 + k;
      const ulonglong2* wr = (const ulonglong2*)we_sm[p];   // warp-broadcast rows
      u64 ch[8];                                            // 8 independent chains
#pragma unroll
      for (int q = 0; q < 8; q++) ch[q] = 0ull;
#pragma unroll
      for (int q = 0; q < 8; q++) {
        ulonglong2 v = wr[q];        // v.x = s(4q,4q+1), v.y = s(4q+2,4q+3)
        fma2(ch[q], v.x, a2[2*q + 0]);
        fma2(ch[q], v.y, a2[2*q + 1]);
      }
      u64 r0 = add2(add2(ch[0], ch[1]), add2(ch[2], ch[3]));
      u64 r1 = add2(add2(ch[4], ch[5]), add2(ch[6], ch[7]));
      float lo, hi;
      upk2(add2(r0, r1), lo, hi);
      ob[(size_t)p * C_] = lo + hi;   // 32 consecutive floats per warp: 128B store
    }
  }
}

// ---------------------------------------------------------------------------
extern "C" void kernel_launch(void* const* d_in, const int* in_sizes, int n_in,
                              void* d_out, int out_size) {
  const float* wc_in    = (const float*)d_in[0];  // weighted_context [128,16,16,1024]
  const float* word_emb = (const float*)d_in[1];  // [128,32,256]
  const float* ck       = (const float*)d_in[2];  // [256,256]
  const float* bias     = (const float*)d_in[3];  // [256]

  float* out  = (float*)d_out;                         // [128,16,16,1024]
  float* attn = out + (size_t)B_ * HW_ * C_;           // [128,1024,32]

  we_proj_kernel<<<B_, 256>>>(word_emb, ck, bias);
  attn_kernel<<<dim3(C_ / TC, B_), 256>>>(wc_in, out, attn);
}

// round 9
// speedup vs baseline: 1.1234x; 1.1234x over previous
#include <cuda_runtime.h>

#define B_   128
#define C_   1024
#define HW_  256
#define S_   32
#define EMB_ 256
#define TC   128    // channels per block (kernel 2)
#define PC   16     // p-rows per smem chunk (kernel 2)
#define NCHUNK (HW_ / PC)   // 16

typedef unsigned long long u64;

// ---- packed f32x2 helpers (sm_103a FFMA2 path) ----
__device__ __forceinline__ u64 pk2(float x, float y) {
  u64 r; asm("mov.b64 %0, {%1, %2};" : "=l"(r) : "f"(x), "f"(y)); return r;
}
__device__ __forceinline__ void upk2(u64 v, float& x, float& y) {
  asm("mov.b64 {%0, %1}, %2;" : "=f"(x), "=f"(y) : "l"(v));
}
__device__ __forceinline__ void fma2(u64& d, u64 a, u64 b) {   // d += a*b (2 lanes)
  asm("fma.rn.f32x2 %0, %1, %2, %0;" : "+l"(d) : "l"(a), "l"(b));
}
__device__ __forceinline__ u64 add2(u64 a, u64 b) {
  u64 r; asm("add.rn.f32x2 %0, %1, %2;" : "=l"(r) : "l"(a), "l"(b)); return r;
}

// we transposed: [b][p][s], 4 MB scratch
__device__ float g_we[(size_t)B_ * HW_ * S_];

// ---------------------------------------------------------------------------
// Kernel 1: we_t[b][p][s] = sum_e word_emb[b][s][e] * ck[e][p] + bias[p]
// Grid (4, B): block = (p-quarter, b). 256 thr: p_loc = t&63, e-slice = t>>6.
// 4-way e-split + smem tree reduce -> 512 CTAs, 64-deep inner loop.
// ---------------------------------------------------------------------------
__global__ __launch_bounds__(256) void we_proj_kernel(
    const float* __restrict__ word_emb,
    const float* __restrict__ ck,
    const float* __restrict__ bias) {
  __shared__ __align__(16) float smem_pool[EMB_ * S_];   // 32 KB
  float (*emb_t)[S_] = (float (*)[S_])smem_pool;          // [e][s]
  u64 (*red)[64][19]  = (u64 (*)[64][19])smem_pool;       // [3][64][19] u64, aliased

  const int b  = blockIdx.y;
  const int ph = blockIdx.x;        // p-quarter 0..3
  const int t  = threadIdx.x;

  const float* wb = word_emb + (size_t)b * S_ * EMB_;
  // transpose-load word_emb[b] into smem
  for (int j = t; j < S_ * EMB_; j += 256) {
    int s = j & (S_ - 1);
    int e = j >> 5;
    emb_t[e][s] = wb[s * EMB_ + e];
  }
  __syncthreads();

  const int p_loc = t & 63;
  const int p     = ph * 64 + p_loc;
  const int eh    = t >> 6;         // e-slice 0..3

  u64 acc2[S_ / 2];
  {
    const u64 init = (eh == 0) ? pk2(bias[p], bias[p]) : 0ull;
#pragma unroll
    for (int q = 0; q < S_ / 2; q++) acc2[q] = init;
  }

#pragma unroll 4
  for (int i = 0; i < EMB_ / 4; i++) {
    const int e = eh * 64 + i;
    const float ckv = ck[e * EMB_ + p];       // coalesced, L2-resident
    const u64 c2 = pk2(ckv, ckv);
    const ulonglong2* er = (const ulonglong2*)emb_t[e];
#pragma unroll
    for (int q = 0; q < 8; q++) {
      ulonglong2 v = er[q];
      fma2(acc2[2*q + 0], v.x, c2);
      fma2(acc2[2*q + 1], v.y, c2);
    }
  }
  __syncthreads();   // all emb_t reads done before red aliases the pool

  if (eh > 0) {
#pragma unroll
    for (int q = 0; q < S_ / 2; q++) red[eh - 1][p_loc][q] = acc2[q];
  }
  __syncthreads();

  if (eh == 0) {
#pragma unroll
    for (int q = 0; q < S_ / 2; q++)
      acc2[q] = add2(add2(acc2[q], red[0][p_loc][q]),
                     add2(red[1][p_loc][q], red[2][p_loc][q]));
    ulonglong2* o = (ulonglong2*)(g_we + ((size_t)b * HW_ + p) * S_);
#pragma unroll
    for (int q = 0; q < 8; q++) {
      ulonglong2 v; v.x = acc2[2*q]; v.y = acc2[2*q + 1];
      o[q] = v;
    }
  }
}

// ---------------------------------------------------------------------------
// Kernel 2 (fused), TC=128 channels per CTA:
//   logits: 4c x 4s per thread (K=256, double-buffered wc chunks)
//   softmax over s (8-lane shuffle groups), attn STG.128 straight from regs
//   epilogue: 2 channels per thread, we-row broadcast amortized over both
// ---------------------------------------------------------------------------
__global__ __launch_bounds__(256, 2) void attn_kernel(
    const float* __restrict__ wc,
    float* __restrict__ out,
    float* __restrict__ attn_out) {
  __shared__ float we_sm[HW_][S_];               // 32 KB: [p][s]
  // 16 KB pool: wc double-buffer [2][PC][TC] (16 KB)  U  attn_t [S_][TC] (16 KB)
  __shared__ __align__(16) float pool[2 * PC * TC];
  float (*attn_t)[TC] = (float (*)[TC])pool;     // [s][c], used after logits

  const int b  = blockIdx.y;
  const int c0 = blockIdx.x * TC;
  const int t  = threadIdx.x;

  // chunk-0 preload (issue LDG early, overlap with we staging)
  const float* wcb = wc + (size_t)b * HW_ * C_ + c0;
  const int ldrow = t >> 5;            // 0..7 (rows ldrow, ldrow+8)
  const int ldcol = (t & 31) << 2;     // 0,4,..,124
  const float* ldsrc0 = wcb + (size_t)ldrow * C_ + ldcol;
  const float* ldsrc1 = wcb + (size_t)(ldrow + 8) * C_ + ldcol;
  float4 pre0 = *(const float4*)ldsrc0;
  float4 pre1 = *(const float4*)ldsrc1;

  // stage we_t[b] (8192 floats) into smem
  {
    const float4* gw = (const float4*)(g_we + (size_t)b * HW_ * S_);
    float4* sw = (float4*)we_sm;
    for (int i = t; i < HW_ * S_ / 4; i += 256) sw[i] = gw[i];
  }
  *(float4*)&pool[ldrow * TC + ldcol]        = pre0;
  *(float4*)&pool[(ldrow + 8) * TC + ldcol]  = pre1;
  __syncthreads();                     // chunk 0 + we_sm visible

  // ---- logits: thread owns c = 4*cg..4*cg+3, s = 4*sg..4*sg+3 ----
  const int cg = t >> 3;   // 0..31
  const int sg = t & 7;    // 0..7
  u64 acc2[4][2];          // [channel][s-pair]
#pragma unroll
  for (int i = 0; i < 4; i++) acc2[i][0] = acc2[i][1] = 0ull;

  for (int pcI = 0; pcI < NCHUNK; pcI++) {
    if (pcI + 1 < NCHUNK) {            // hide next chunk's LDG behind compute
      pre0 = *(const float4*)(ldsrc0 + (size_t)(pcI + 1) * PC * C_);
      pre1 = *(const float4*)(ldsrc1 + (size_t)(pcI + 1) * PC * C_);
    }
    const float* buf = pool + (pcI & 1) * (PC * TC);
#pragma unroll
    for (int pp = 0; pp < PC; pp++) {
      float4 w = *(const float4*)&buf[pp * TC + cg * 4];      // 4 channels
      ulonglong2 v = *(const ulonglong2*)&we_sm[pcI * PC + pp][sg * 4];
      const u64 w0 = pk2(w.x, w.x), w1 = pk2(w.y, w.y);
      const u64 w2 = pk2(w.z, w.z), w3 = pk2(w.w, w.w);
      fma2(acc2[0][0], v.x, w0);  fma2(acc2[0][1], v.y, w0);
      fma2(acc2[1][0], v.x, w1);  fma2(acc2[1][1], v.y, w1);
      fma2(acc2[2][0], v.x, w2);  fma2(acc2[2][1], v.y, w2);
      fma2(acc2[3][0], v.x, w3);  fma2(acc2[3][1], v.y, w3);
    }
    if (pcI + 1 < NCHUNK) {
      float* nb = pool + ((pcI + 1) & 1) * (PC * TC);
      *(float4*)&nb[ldrow * TC + ldcol]       = pre0;
      *(float4*)&nb[(ldrow + 8) * TC + ldcol] = pre1;
    }
    __syncthreads();                   // one barrier per chunk
  }

  // ---- softmax over s per channel (8-lane aligned shuffle groups) ----
  float av[4][4];
#pragma unroll
  for (int i = 0; i < 4; i++) {
    upk2(acc2[i][0], av[i][0], av[i][1]);
    upk2(acc2[i][1], av[i][2], av[i][3]);
  }
#pragma unroll
  for (int i = 0; i < 4; i++) {
    float m = fmaxf(fmaxf(av[i][0], av[i][1]), fmaxf(av[i][2], av[i][3]));
#pragma unroll
    for (int o = 1; o < 8; o <<= 1) m = fmaxf(m, __shfl_xor_sync(0xffffffffu, m, o));
    float sum = 0.f;
#pragma unroll
    for (int j = 0; j < 4; j++) { av[i][j] = __expf(av[i][j] - m); sum += av[i][j]; }
#pragma unroll
    for (int o = 1; o < 8; o <<= 1) sum += __shfl_xor_sync(0xffffffffu, sum, o);
    const float inv = 1.f / sum;
#pragma unroll
    for (int j = 0; j < 4; j++) av[i][j] *= inv;
  }

  // ---- attn -> gmem straight from registers: attn[b][c][4sg..4sg+3] ----
  {
    float* ab = attn_out + ((size_t)b * C_ + c0 + cg * 4) * S_ + sg * 4;
#pragma unroll
    for (int i = 0; i < 4; i++)
      *(float4*)(ab + (size_t)i * S_) = make_float4(av[i][0], av[i][1], av[i][2], av[i][3]);
  }

  // ---- attn_t[s][c] into the (now dead) pool ----
#pragma unroll
  for (int j = 0; j < 4; j++)
    *(float4*)&attn_t[sg * 4 + j][cg * 4] =
        make_float4(av[0][j], av[1][j], av[2][j], av[3][j]);
  __syncthreads();

  // ---- epilogue: out[b][p][c0+oc(+64)] = sum_s we_sm[p][s] * attn[c][s] ----
  {
    const int oc = t & 63;             // 2 channels: oc, oc+64
    const int pg = t >> 6;             // 0..3 -> 64 p each
    u64 a2a[S_ / 2], a2b[S_ / 2];      // packed attn pairs per channel
#pragma unroll
    for (int q = 0; q < S_ / 2; q++) {
      a2a[q] = pk2(attn_t[2*q][oc],      attn_t[2*q + 1][oc]);
      a2b[q] = pk2(attn_t[2*q][oc + 64], attn_t[2*q + 1][oc + 64]);
    }
    float* ob = out + (size_t)b * HW_ * C_ + c0 + oc;
#pragma unroll 2
    for (int k = 0; k < 64; k++) {
      const int p = pg * 64 + k;
      const ulonglong2* wr = (const ulonglong2*)we_sm[p];  // warp-broadcast row
      u64 cha[4], chb[4];
#pragma unroll
      for (int q = 0; q < 4; q++) { cha[q] = 0ull; chb[q] = 0ull; }
#pragma unroll
      for (int q4 = 0; q4 < 8; q4++) {
        ulonglong2 v = wr[q4];         // v.x = s(4q4,4q4+1), v.y = s(4q4+2,4q4+3)
        fma2(cha[q4 & 3], v.x, a2a[2*q4 + 0]);
        fma2(cha[q4 & 3], v.y, a2a[2*q4 + 1]);
        fma2(chb[q4 & 3], v.x, a2b[2*q4 + 0]);
        fma2(chb[q4 & 3], v.y, a2b[2*q4 + 1]);
      }
      u64 ra = add2(add2(cha[0], cha[1]), add2(cha[2], cha[3]));
      u64 rb = add2(add2(chb[0], chb[1]), add2(chb[2], chb[3]));
      float lo, hi;
      upk2(ra, lo, hi);
      ob[(size_t)p * C_] = lo + hi;          // coalesced 128B per warp
      upk2(rb, lo, hi);
      ob[(size_t)p * C_ + 64] = lo + hi;
    }
  }
}

// ---------------------------------------------------------------------------
extern "C" void kernel_launch(void* const* d_in, const int* in_sizes, int n_in,
                              void* d_out, int out_size) {
  const float* wc_in    = (const float*)d_in[0];  // weighted_context [128,16,16,1024]
  const float* word_emb = (const float*)d_in[1];  // [128,32,256]
  const float* ck       = (const float*)d_in[2];  // [256,256]
  const float* bias     = (const float*)d_in[3];  // [256]

  float* out  = (float*)d_out;                         // [128,16,16,1024]
  float* attn = out + (size_t)B_ * HW_ * C_;           // [128,1024,32]

  we_proj_kernel<<<dim3(4, B_), 256>>>(word_emb, ck, bias);
  attn_kernel<<<dim3(C_ / TC, B_), 256>>>(wc_in, out, attn);
}